// round 13
// baseline (speedup 1.0000x reference)
#include <cuda_runtime.h>
#include <cuda_bf16.h>

#define NPTS 4096
#define BATCH 8
#define KNBR 30
#define NEG_SLOPE 0.2f
#define FULL 0xFFFFFFFFu

typedef unsigned long long u64;
typedef unsigned int u32;

// scratch: neighbor indices [B, N, 30]
__device__ int g_idx[BATCH * NPTS * KNBR];

__device__ __forceinline__ u32 fkey(float f) {
    u32 u = __float_as_uint(f);
    u32 mask = (u32)(((int)u) >> 31) | 0x80000000u;
    return u ^ mask;
}
__device__ __forceinline__ float unfkey(u32 hb) {
    u32 u = (hb & 0x80000000u) ? (hb ^ 0x80000000u) : ~hb;
    return __uint_as_float(u);
}

__device__ __forceinline__ float lrelu(float v) {
    return v > 0.0f ? v : NEG_SLOPE * v;
}

__device__ __forceinline__ u64 pack2(float lo, float hi) {
    u64 r;
    asm("mov.b64 %0, {%1, %2};" : "=l"(r) : "f"(lo), "f"(hi));
    return r;
}
__device__ __forceinline__ void unpack2(u64 v, float& lo, float& hi) {
    asm("mov.b64 {%0, %1}, %2;" : "=f"(lo), "=f"(hi) : "l"(v));
}
__device__ __forceinline__ u64 fma2(u64 a, u64 b, u64 c) {
    u64 d;
    asm("fma.rn.f32x2 %0, %1, %2, %3;" : "=l"(d) : "l"(a), "l"(b), "l"(c));
    return d;
}
__device__ __forceinline__ u64 mul2(u64 a, u64 b) {
    u64 d;
    asm("mul.rn.f32x2 %0, %1, %2;" : "=l"(d) : "l"(a), "l"(b));
    return d;
}
__device__ __forceinline__ u64 lrelu2(u64 v) {
    float lo, hi;
    unpack2(v, lo, hi);
    return pack2(lrelu(lo), lrelu(hi));
}
__device__ __forceinline__ u32 f2tf32(float f) {
    u32 r;
    asm("cvt.rna.tf32.f32 %0, %1;" : "=r"(r) : "f"(f));
    return r;
}

#define LDSM_X4(r0, r1, r2, r3, addr)                                        \
    asm volatile("ldmatrix.sync.aligned.m8n8.x4.shared.b16 {%0,%1,%2,%3}, [%4];" \
                 : "=r"(r0), "=r"(r1), "=r"(r2), "=r"(r3) : "r"(addr))
#define LDSM_X2(r0, r1, addr)                                                \
    asm volatile("ldmatrix.sync.aligned.m8n8.x2.shared.b16 {%0,%1}, [%2];"   \
                 : "=r"(r0), "=r"(r1) : "r"(addr))
#define MMA_TF32(d0, d1, d2, d3, a0, a1, a2, a3, b0, b1)                     \
    asm volatile("mma.sync.aligned.m16n8k8.row.col.f32.tf32.tf32.f32 "       \
                 "{%0,%1,%2,%3},{%4,%5,%6,%7},{%8,%9},{%0,%1,%2,%3};"        \
                 : "+f"(d0), "+f"(d1), "+f"(d2), "+f"(d3)                    \
                 : "r"(a0), "r"(a1), "r"(a2), "r"(a3), "r"(b0), "r"(b1))

// ---------------------------------------------------------------------------
// Kernel 1: KNN — warp-per-2-queries, float prefilter (R11, proven),
// parameterized by batch offset for chunked pipelining.
// ---------------------------------------------------------------------------
__global__ void __launch_bounds__(512) knn_kernel(const float* __restrict__ x,
                                                  int b0) {
    extern __shared__ float4 p4[];
    const int b = b0 + blockIdx.y;
    const int tid = threadIdx.x;
    const int wid = tid >> 5;
    const int lane = tid & 31;
    const float* xb = x + b * 3 * NPTS;

    for (int i = tid; i < NPTS; i += 512) {
        float cx = xb[i], cy = xb[NPTS + i], cz = xb[2 * NPTS + i];
        p4[i] = make_float4(cx, cy, cz, cx * cx + cy * cy + cz * cz);
    }
    __syncthreads();

    for (int t = 0; t < 2; ++t) {
        const int qA = blockIdx.x * 64 + wid * 4 + t;
        const int qB = qA + 2;
        const float4 qvA = p4[qA];
        const float4 qvB = p4[qB];
        const float qqA = qvA.w, qqB = qvB.w;

        u64 LA = 0ull, LB = 0ull;
        float thrFA = __int_as_float(0xff800000);
        float thrFB = __int_as_float(0xff800000);

#pragma unroll 2
        for (int base = 0; base < NPTS; base += 32) {
            const int c = base + lane;
            const float4 cv = p4[c];
            float dA = qvA.x * cv.x;
            dA = fmaf(qvA.y, cv.y, dA);
            dA = fmaf(qvA.z, cv.z, dA);
            float dB = qvB.x * cv.x;
            dB = fmaf(qvB.y, cv.y, dB);
            dB = fmaf(qvB.z, cv.z, dB);
            const float pdA = fmaf(2.0f, dA, -qqA) - cv.w;
            const float pdB = fmaf(2.0f, dB, -qqB) - cv.w;

            unsigned mA = __ballot_sync(FULL, pdA >= thrFA);
            unsigned mB = __ballot_sync(FULL, pdB >= thrFB);
            if (mA | mB) {
                const u32 ic = (u32)(~c);
                const u64 keyA = ((u64)fkey(pdA) << 32) | ic;
                const u64 keyB = ((u64)fkey(pdB) << 32) | ic;
                while (mA) {
                    const int src = __ffs(mA) - 1;
                    mA &= mA - 1;
                    const u64 k = __shfl_sync(FULL, keyA, src);
                    u64 prev = __shfl_up_sync(FULL, LA, 1);
                    if (lane == 0) prev = ~0ull;
                    LA = (LA > k) ? LA : ((prev > k) ? k : prev);
                }
                while (mB) {
                    const int src = __ffs(mB) - 1;
                    mB &= mB - 1;
                    const u64 k = __shfl_sync(FULL, keyB, src);
                    u64 prev = __shfl_up_sync(FULL, LB, 1);
                    if (lane == 0) prev = ~0ull;
                    LB = (LB > k) ? LB : ((prev > k) ? k : prev);
                }
                const u64 thrA = __shfl_sync(FULL, LA, 29);
                const u64 thrB = __shfl_sync(FULL, LB, 29);
                thrFA = unfkey((u32)(thrA >> 32));
                thrFB = unfkey((u32)(thrB >> 32));
            }
        }

        if (lane < KNBR) {
            g_idx[(b * NPTS + qA) * KNBR + lane] = (int)(~(u32)LA);
            g_idx[(b * NPTS + qB) * KNBR + lane] = (int)(~(u32)LB);
        }
        __syncwarp();
    }
}

// ---------------------------------------------------------------------------
// Kernel 2: fused edge-MLP; layer-2 on tensor cores (tf32, hi/lo comp).
// Byte-identical math to R9 (proven 159us); parameterized by point offset.
// ---------------------------------------------------------------------------
#define SM_WHI 0
#define SM_WLO 17408
#define SM_W1  34816
#define SM_H1  36864
#define SM_AJ  71680
#define MLP_SMEM 72704

__global__ void __launch_bounds__(128, 3) mlp_kernel(
    const float* __restrict__ x,
    const float* __restrict__ w1, const float* __restrict__ g1, const float* __restrict__ b1,
    const float* __restrict__ w2, const float* __restrict__ g2, const float* __restrict__ b2,
    const float* __restrict__ wa, const float* __restrict__ ba,
    const float* __restrict__ ga, const float* __restrict__ bga,
    float* __restrict__ out, int p0)
{
    extern __shared__ __align__(16) unsigned char smraw[];
    u32*   whi   = (u32*)(smraw + SM_WHI);
    u32*   wlo   = (u32*)(smraw + SM_WLO);
    u64*   w1row = (u64*)(smraw + SM_W1);
    float* h1b   = (float*)(smraw + SM_H1);
    float* ajwb  = (float*)(smraw + SM_AJ);

    const int tid = threadIdx.x;
    const int wid = tid >> 5;
    const int lane = tid & 31;
    const int grp = lane >> 2;
    const int tig = lane & 3;
    const float rs = rsqrtf(1.0f + 1e-5f);

    for (int idx = tid; idx < 4096; idx += 128) {
        const int c = idx >> 6, k = idx & 63;
        const float w = w2[idx];
        const u32 hb = f2tf32(w);
        const float hf = __uint_as_float(hb);
        whi[c * 68 + k] = hb;
        wlo[c * 68 + k] = f2tf32(w - hf);
    }
    if (tid < 96) {
        const int cp = tid / 3;
        const int i0 = (tid % 3) * 2;
        w1row[cp * 8 + i0] = pack2(w1[(2 * cp) * 6 + i0], w1[(2 * cp + 1) * 6 + i0]);
        w1row[cp * 8 + i0 + 1] = pack2(w1[(2 * cp) * 6 + i0 + 1], w1[(2 * cp + 1) * 6 + i0 + 1]);
    }
    if (tid < 32) {
        w1row[tid * 8 + 6] = pack2(g1[2 * tid] * rs, g1[2 * tid + 1] * rs);
        w1row[tid * 8 + 7] = pack2(b1[2 * tid], b1[2 * tid + 1]);
    }
    __syncthreads();

    float s2r[8], b2r[8], wa8[8];
#pragma unroll
    for (int m = 0; m < 4; ++m) {
        const int r0 = m * 16 + grp, r1 = r0 + 8;
        s2r[2 * m] = g2[r0] * rs;     s2r[2 * m + 1] = g2[r1] * rs;
        b2r[2 * m] = b2[r0];          b2r[2 * m + 1] = b2[r1];
        wa8[2 * m] = wa[r0];          wa8[2 * m + 1] = wa[r1];
    }
    const float ba0 = ba[0];
    const float sa = ga[0] * rs;
    const float bza = bga[0];

    const u32 sb = (u32)__cvta_generic_to_shared(smraw);
    const u32 h1base = sb + SM_H1 + (u32)(wid * 32 * 68 * 4);
    const u32 a_off = (u32)((((lane & 15) * 68) + ((lane >> 4) * 4)) * 4);
    const u32 b_off = (u32)((((lane & 7) * 68) + (((lane >> 3) & 1) * 4)) * 4);
    const u32 ahi_base = sb + SM_WHI + a_off;
    const u32 alo_base = sb + SM_WLO + a_off;
    const u32 b_base = h1base + b_off;

    float* aj_sm = ajwb + wid * 64;
    float* wrow = aj_sm + 32;

    for (int tt = 0; tt < 8; ++tt) {
        const int p = p0 + blockIdx.x * 32 + wid * 8 + tt;
        const int bb = p >> 12;
        const int np = p & (NPTS - 1);
        const float* xb = x + bb * 3 * NPTS;
        const float cx = xb[np], cy = xb[NPTS + np], cz = xb[2 * NPTS + np];
        const int nb = (lane < KNBR) ? g_idx[(bb * NPTS + np) * KNBR + lane] : np;

        u64 f2[6];
        {
            const float fx = xb[nb] - cx, fy = xb[NPTS + nb] - cy, fz = xb[2 * NPTS + nb] - cz;
            f2[0] = pack2(fx, fx); f2[1] = pack2(fy, fy); f2[2] = pack2(fz, fz);
            f2[3] = pack2(cx, cx); f2[4] = pack2(cy, cy); f2[5] = pack2(cz, cz);
        }

        __syncwarp();
        {
            float* h1row = h1b + (wid * 32 + lane) * 68;
#pragma unroll
            for (int cp = 0; cp < 32; ++cp) {
                const ulonglong4* r4 = (const ulonglong4*)(w1row + cp * 8);
                const ulonglong4 r0 = r4[0];
                const ulonglong4 r1 = r4[1];
                u64 a = mul2(r0.x, f2[0]);
                a = fma2(r0.y, f2[1], a); a = fma2(r0.z, f2[2], a);
                a = fma2(r0.w, f2[3], a); a = fma2(r1.x, f2[4], a);
                a = fma2(r1.y, f2[5], a);
                *(u64*)&h1row[2 * cp] = lrelu2(fma2(a, r1.z, r1.w));
            }
        }
        __syncwarp();

        float d[4][4][4];
#pragma unroll
        for (int m = 0; m < 4; ++m)
#pragma unroll
            for (int n = 0; n < 4; ++n)
#pragma unroll
                for (int i = 0; i < 4; ++i) d[m][n][i] = 0.0f;

#pragma unroll
        for (int k = 0; k < 8; ++k) {
            u32 Bf[4][2];
#pragma unroll
            for (int n = 0; n < 4; ++n)
                LDSM_X2(Bf[n][0], Bf[n][1], b_base + (u32)((n * 8 * 68 + k * 8) * 4));
            u32 Ah[4][4], Al[4][4];
#pragma unroll
            for (int m = 0; m < 4; ++m) {
                const u32 ao = (u32)((m * 16 * 68 + k * 8) * 4);
                LDSM_X4(Ah[m][0], Ah[m][1], Ah[m][2], Ah[m][3], ahi_base + ao);
                LDSM_X4(Al[m][0], Al[m][1], Al[m][2], Al[m][3], alo_base + ao);
            }
#pragma unroll
            for (int m = 0; m < 4; ++m)
#pragma unroll
                for (int n = 0; n < 4; ++n) {
                    MMA_TF32(d[m][n][0], d[m][n][1], d[m][n][2], d[m][n][3],
                             Ah[m][0], Ah[m][1], Ah[m][2], Ah[m][3], Bf[n][0], Bf[n][1]);
                    MMA_TF32(d[m][n][0], d[m][n][1], d[m][n][2], d[m][n][3],
                             Al[m][0], Al[m][1], Al[m][2], Al[m][3], Bf[n][0], Bf[n][1]);
                }
        }

#pragma unroll
        for (int m = 0; m < 4; ++m)
#pragma unroll
            for (int n = 0; n < 4; ++n) {
                d[m][n][0] = lrelu(fmaf(d[m][n][0], s2r[2 * m], b2r[2 * m]));
                d[m][n][1] = lrelu(fmaf(d[m][n][1], s2r[2 * m], b2r[2 * m]));
                d[m][n][2] = lrelu(fmaf(d[m][n][2], s2r[2 * m + 1], b2r[2 * m + 1]));
                d[m][n][3] = lrelu(fmaf(d[m][n][3], s2r[2 * m + 1], b2r[2 * m + 1]));
            }

        float p0f[4], p1f[4];
#pragma unroll
        for (int n = 0; n < 4; ++n) { p0f[n] = 0.0f; p1f[n] = 0.0f; }
#pragma unroll
        for (int m = 0; m < 4; ++m)
#pragma unroll
            for (int n = 0; n < 4; ++n) {
                p0f[n] = fmaf(wa8[2 * m], d[m][n][0], p0f[n]);
                p0f[n] = fmaf(wa8[2 * m + 1], d[m][n][2], p0f[n]);
                p1f[n] = fmaf(wa8[2 * m], d[m][n][1], p1f[n]);
                p1f[n] = fmaf(wa8[2 * m + 1], d[m][n][3], p1f[n]);
            }
#pragma unroll
        for (int n = 0; n < 4; ++n) {
#pragma unroll
            for (int off = 4; off < 32; off <<= 1) {
                p0f[n] += __shfl_xor_sync(FULL, p0f[n], off);
                p1f[n] += __shfl_xor_sync(FULL, p1f[n], off);
            }
        }
        if (lane < 4) {
#pragma unroll
            for (int n = 0; n < 4; ++n) {
                aj_sm[n * 8 + 2 * lane] = p0f[n];
                aj_sm[n * 8 + 2 * lane + 1] = p1f[n];
            }
        }
        __syncwarp();
        float aj = aj_sm[lane];

        aj = lrelu(fmaf(aj + ba0, sa, bza));
        if (lane >= KNBR) aj = -1e30f;
        float mx = aj;
#pragma unroll
        for (int off = 16; off; off >>= 1)
            mx = fmaxf(mx, __shfl_xor_sync(FULL, mx, off));
        const float e = __expf(aj - mx);
        float scn = e;
#pragma unroll
        for (int off = 1; off < 32; off <<= 1) {
            const float v = __shfl_up_sync(FULL, scn, off);
            if (lane >= off) scn += v;
        }
        const float d10 = __shfl_sync(FULL, scn, 9);
        const float d20 = __shfl_sync(FULL, scn, 19);
        const float d30 = __shfl_sync(FULL, scn, 29);
        float ws = 0.0f;
        if (lane < 10) ws += 1.0f / d10;
        if (lane < 20) ws += 1.0f / d20;
        if (lane < 30) ws += 1.0f / d30;
        wrow[lane] = e * ws * (1.0f / 3.0f);
        __syncwarp();

        float w0[4], w1v[4];
#pragma unroll
        for (int n = 0; n < 4; ++n) {
            w0[n] = wrow[n * 8 + 2 * tig];
            w1v[n] = wrow[n * 8 + 2 * tig + 1];
        }
#pragma unroll
        for (int m = 0; m < 4; ++m) {
            float o0 = 0.0f, o1 = 0.0f;
#pragma unroll
            for (int n = 0; n < 4; ++n) {
                o0 = fmaf(d[m][n][0], w0[n], o0);
                o0 = fmaf(d[m][n][1], w1v[n], o0);
                o1 = fmaf(d[m][n][2], w0[n], o1);
                o1 = fmaf(d[m][n][3], w1v[n], o1);
            }
            o0 += __shfl_xor_sync(FULL, o0, 1);
            o0 += __shfl_xor_sync(FULL, o0, 2);
            o1 += __shfl_xor_sync(FULL, o1, 1);
            o1 += __shfl_xor_sync(FULL, o1, 2);
            if (tig == 0) {
                const int row = m * 16 + grp;
                out[(bb * 64 + row) * NPTS + np] = o0;
                out[(bb * 64 + row + 8) * NPTS + np] = o1;
            }
        }
        __syncwarp();
    }
}

extern "C" void kernel_launch(void* const* d_in, const int* in_sizes, int n_in,
                              void* d_out, int out_size) {
    const float* x   = (const float*)d_in[0];
    const float* w1  = (const float*)d_in[1];
    const float* g1  = (const float*)d_in[2];
    const float* b1  = (const float*)d_in[3];
    const float* w2  = (const float*)d_in[4];
    const float* g2  = (const float*)d_in[5];
    const float* b2  = (const float*)d_in[6];
    const float* wa  = (const float*)d_in[7];
    const float* ba  = (const float*)d_in[8];
    const float* ga  = (const float*)d_in[9];
    const float* bga = (const float*)d_in[10];
    float* out = (float*)d_out;

    // one-time host-side resources (no device memory involved; the GPU work
    // enqueued per call is identical every call)
    static cudaStream_t sK = nullptr;
    static cudaEvent_t evFork = nullptr;
    static cudaEvent_t evK[4] = {nullptr, nullptr, nullptr, nullptr};
    static bool cfg_done = false;
    if (sK == nullptr) {
        cudaStreamCreateWithFlags(&sK, cudaStreamNonBlocking);
        cudaEventCreateWithFlags(&evFork, cudaEventDisableTiming);
        for (int c = 0; c < 4; ++c)
            cudaEventCreateWithFlags(&evK[c], cudaEventDisableTiming);
    }
    const int knn_smem = NPTS * 16;  // 64KB dynamic
    if (!cfg_done) {
        cudaFuncSetAttribute(knn_kernel, cudaFuncAttributeMaxDynamicSharedMemorySize, knn_smem);
        cudaFuncSetAttribute(mlp_kernel, cudaFuncAttributeMaxDynamicSharedMemorySize, MLP_SMEM);
        cfg_done = true;
    }

    // fork: side stream runs all KNN chunks; main stream runs MLP chunks,
    // each gated on its KNN chunk's event. MLP chunks 0-2 overlap KNN 1-3.
    cudaEventRecord(evFork, 0);
    cudaStreamWaitEvent(sK, evFork, 0);
    for (int c = 0; c < 4; ++c) {
        knn_kernel<<<dim3(NPTS / 64, 2), 512, knn_smem, sK>>>(x, c * 2);
        cudaEventRecord(evK[c], sK);
    }
    for (int c = 0; c < 4; ++c) {
        cudaStreamWaitEvent(0, evK[c], 0);
        mlp_kernel<<<(2 * NPTS) / 32, 128, MLP_SMEM>>>(x, w1, g1, b1, w2, g2, b2,
                                                       wa, ba, ga, bga, out,
                                                       c * 2 * NPTS);
    }
}

// round 14
// speedup vs baseline: 1.2081x; 1.2081x over previous
#include <cuda_runtime.h>
#include <cuda_bf16.h>

#define NPTS 4096
#define BATCH 8
#define KNBR 30
#define NEG_SLOPE 0.2f
#define FULL 0xFFFFFFFFu

typedef unsigned long long u64;
typedef unsigned int u32;

// scratch: neighbor indices [B, N, 30]
__device__ int g_idx[BATCH * NPTS * KNBR];

__device__ __forceinline__ u32 fkey(float f) {
    u32 u = __float_as_uint(f);
    u32 mask = (u32)(((int)u) >> 31) | 0x80000000u;
    return u ^ mask;
}
__device__ __forceinline__ float unfkey(u32 hb) {
    u32 u = (hb & 0x80000000u) ? (hb ^ 0x80000000u) : ~hb;
    return __uint_as_float(u);
}

__device__ __forceinline__ float lrelu(float v) {
    return v > 0.0f ? v : NEG_SLOPE * v;
}

__device__ __forceinline__ u64 pack2(float lo, float hi) {
    u64 r;
    asm("mov.b64 %0, {%1, %2};" : "=l"(r) : "f"(lo), "f"(hi));
    return r;
}
__device__ __forceinline__ void unpack2(u64 v, float& lo, float& hi) {
    asm("mov.b64 {%0, %1}, %2;" : "=f"(lo), "=f"(hi) : "l"(v));
}
__device__ __forceinline__ u64 fma2(u64 a, u64 b, u64 c) {
    u64 d;
    asm("fma.rn.f32x2 %0, %1, %2, %3;" : "=l"(d) : "l"(a), "l"(b), "l"(c));
    return d;
}
__device__ __forceinline__ u64 mul2(u64 a, u64 b) {
    u64 d;
    asm("mul.rn.f32x2 %0, %1, %2;" : "=l"(d) : "l"(a), "l"(b));
    return d;
}
__device__ __forceinline__ u64 lrelu2(u64 v) {
    float lo, hi;
    unpack2(v, lo, hi);
    return pack2(lrelu(lo), lrelu(hi));
}
__device__ __forceinline__ u32 f2tf32(float f) {
    u32 r;
    asm("cvt.rna.tf32.f32 %0, %1;" : "=r"(r) : "f"(f));
    return r;
}

#define LDSM_X4(r0, r1, r2, r3, addr)                                        \
    asm volatile("ldmatrix.sync.aligned.m8n8.x4.shared.b16 {%0,%1,%2,%3}, [%4];" \
                 : "=r"(r0), "=r"(r1), "=r"(r2), "=r"(r3) : "r"(addr))
#define LDSM_X2(r0, r1, addr)                                                \
    asm volatile("ldmatrix.sync.aligned.m8n8.x2.shared.b16 {%0,%1}, [%2];"   \
                 : "=r"(r0), "=r"(r1) : "r"(addr))
#define MMA_TF32(d0, d1, d2, d3, a0, a1, a2, a3, b0, b1)                     \
    asm volatile("mma.sync.aligned.m16n8k8.row.col.f32.tf32.tf32.f32 "       \
                 "{%0,%1,%2,%3},{%4,%5,%6,%7},{%8,%9},{%0,%1,%2,%3};"        \
                 : "+f"(d0), "+f"(d1), "+f"(d2), "+f"(d3)                    \
                 : "r"(a0), "r"(a1), "r"(a2), "r"(a3), "r"(b0), "r"(b1))

// ---------------------------------------------------------------------------
// Kernel 1: KNN — warp-per-2-queries, float prefilter (R11, proven),
// parameterized by batch offset for chunked pipelining.
// ---------------------------------------------------------------------------
__global__ void __launch_bounds__(512) knn_kernel(const float* __restrict__ x,
                                                  int b0) {
    extern __shared__ float4 p4[];
    const int b = b0 + blockIdx.y;
    const int tid = threadIdx.x;
    const int wid = tid >> 5;
    const int lane = tid & 31;
    const float* xb = x + b * 3 * NPTS;

    for (int i = tid; i < NPTS; i += 512) {
        float cx = xb[i], cy = xb[NPTS + i], cz = xb[2 * NPTS + i];
        p4[i] = make_float4(cx, cy, cz, cx * cx + cy * cy + cz * cz);
    }
    __syncthreads();

    for (int t = 0; t < 2; ++t) {
        const int qA = blockIdx.x * 64 + wid * 4 + t;
        const int qB = qA + 2;
        const float4 qvA = p4[qA];
        const float4 qvB = p4[qB];
        const float qqA = qvA.w, qqB = qvB.w;

        u64 LA = 0ull, LB = 0ull;
        float thrFA = __int_as_float(0xff800000);
        float thrFB = __int_as_float(0xff800000);

#pragma unroll 2
        for (int base = 0; base < NPTS; base += 32) {
            const int c = base + lane;
            const float4 cv = p4[c];
            float dA = qvA.x * cv.x;
            dA = fmaf(qvA.y, cv.y, dA);
            dA = fmaf(qvA.z, cv.z, dA);
            float dB = qvB.x * cv.x;
            dB = fmaf(qvB.y, cv.y, dB);
            dB = fmaf(qvB.z, cv.z, dB);
            const float pdA = fmaf(2.0f, dA, -qqA) - cv.w;
            const float pdB = fmaf(2.0f, dB, -qqB) - cv.w;

            unsigned mA = __ballot_sync(FULL, pdA >= thrFA);
            unsigned mB = __ballot_sync(FULL, pdB >= thrFB);
            if (mA | mB) {
                const u32 ic = (u32)(~c);
                const u64 keyA = ((u64)fkey(pdA) << 32) | ic;
                const u64 keyB = ((u64)fkey(pdB) << 32) | ic;
                while (mA) {
                    const int src = __ffs(mA) - 1;
                    mA &= mA - 1;
                    const u64 k = __shfl_sync(FULL, keyA, src);
                    u64 prev = __shfl_up_sync(FULL, LA, 1);
                    if (lane == 0) prev = ~0ull;
                    LA = (LA > k) ? LA : ((prev > k) ? k : prev);
                }
                while (mB) {
                    const int src = __ffs(mB) - 1;
                    mB &= mB - 1;
                    const u64 k = __shfl_sync(FULL, keyB, src);
                    u64 prev = __shfl_up_sync(FULL, LB, 1);
                    if (lane == 0) prev = ~0ull;
                    LB = (LB > k) ? LB : ((prev > k) ? k : prev);
                }
                const u64 thrA = __shfl_sync(FULL, LA, 29);
                const u64 thrB = __shfl_sync(FULL, LB, 29);
                thrFA = unfkey((u32)(thrA >> 32));
                thrFB = unfkey((u32)(thrB >> 32));
            }
        }

        if (lane < KNBR) {
            g_idx[(b * NPTS + qA) * KNBR + lane] = (int)(~(u32)LA);
            g_idx[(b * NPTS + qB) * KNBR + lane] = (int)(~(u32)LB);
        }
        __syncwarp();
    }
}

// ---------------------------------------------------------------------------
// Kernel 2: fused edge-MLP; layer-2 on tensor cores (tf32, hi/lo comp).
// Byte-identical math to R9 (proven 159us); parameterized by point offset.
// ---------------------------------------------------------------------------
#define SM_WHI 0
#define SM_WLO 17408
#define SM_W1  34816
#define SM_H1  36864
#define SM_AJ  71680
#define MLP_SMEM 72704

__global__ void __launch_bounds__(128, 3) mlp_kernel(
    const float* __restrict__ x,
    const float* __restrict__ w1, const float* __restrict__ g1, const float* __restrict__ b1,
    const float* __restrict__ w2, const float* __restrict__ g2, const float* __restrict__ b2,
    const float* __restrict__ wa, const float* __restrict__ ba,
    const float* __restrict__ ga, const float* __restrict__ bga,
    float* __restrict__ out, int p0)
{
    extern __shared__ __align__(16) unsigned char smraw[];
    u32*   whi   = (u32*)(smraw + SM_WHI);
    u32*   wlo   = (u32*)(smraw + SM_WLO);
    u64*   w1row = (u64*)(smraw + SM_W1);
    float* h1b   = (float*)(smraw + SM_H1);
    float* ajwb  = (float*)(smraw + SM_AJ);

    const int tid = threadIdx.x;
    const int wid = tid >> 5;
    const int lane = tid & 31;
    const int grp = lane >> 2;
    const int tig = lane & 3;
    const float rs = rsqrtf(1.0f + 1e-5f);

    for (int idx = tid; idx < 4096; idx += 128) {
        const int c = idx >> 6, k = idx & 63;
        const float w = w2[idx];
        const u32 hb = f2tf32(w);
        const float hf = __uint_as_float(hb);
        whi[c * 68 + k] = hb;
        wlo[c * 68 + k] = f2tf32(w - hf);
    }
    if (tid < 96) {
        const int cp = tid / 3;
        const int i0 = (tid % 3) * 2;
        w1row[cp * 8 + i0] = pack2(w1[(2 * cp) * 6 + i0], w1[(2 * cp + 1) * 6 + i0]);
        w1row[cp * 8 + i0 + 1] = pack2(w1[(2 * cp) * 6 + i0 + 1], w1[(2 * cp + 1) * 6 + i0 + 1]);
    }
    if (tid < 32) {
        w1row[tid * 8 + 6] = pack2(g1[2 * tid] * rs, g1[2 * tid + 1] * rs);
        w1row[tid * 8 + 7] = pack2(b1[2 * tid], b1[2 * tid + 1]);
    }
    __syncthreads();

    float s2r[8], b2r[8], wa8[8];
#pragma unroll
    for (int m = 0; m < 4; ++m) {
        const int r0 = m * 16 + grp, r1 = r0 + 8;
        s2r[2 * m] = g2[r0] * rs;     s2r[2 * m + 1] = g2[r1] * rs;
        b2r[2 * m] = b2[r0];          b2r[2 * m + 1] = b2[r1];
        wa8[2 * m] = wa[r0];          wa8[2 * m + 1] = wa[r1];
    }
    const float ba0 = ba[0];
    const float sa = ga[0] * rs;
    const float bza = bga[0];

    const u32 sb = (u32)__cvta_generic_to_shared(smraw);
    const u32 h1base = sb + SM_H1 + (u32)(wid * 32 * 68 * 4);
    const u32 a_off = (u32)((((lane & 15) * 68) + ((lane >> 4) * 4)) * 4);
    const u32 b_off = (u32)((((lane & 7) * 68) + (((lane >> 3) & 1) * 4)) * 4);
    const u32 ahi_base = sb + SM_WHI + a_off;
    const u32 alo_base = sb + SM_WLO + a_off;
    const u32 b_base = h1base + b_off;

    float* aj_sm = ajwb + wid * 64;
    float* wrow = aj_sm + 32;

    for (int tt = 0; tt < 8; ++tt) {
        const int p = p0 + blockIdx.x * 32 + wid * 8 + tt;
        const int bb = p >> 12;
        const int np = p & (NPTS - 1);
        const float* xb = x + bb * 3 * NPTS;
        const float cx = xb[np], cy = xb[NPTS + np], cz = xb[2 * NPTS + np];
        const int nb = (lane < KNBR) ? g_idx[(bb * NPTS + np) * KNBR + lane] : np;

        u64 f2[6];
        {
            const float fx = xb[nb] - cx, fy = xb[NPTS + nb] - cy, fz = xb[2 * NPTS + nb] - cz;
            f2[0] = pack2(fx, fx); f2[1] = pack2(fy, fy); f2[2] = pack2(fz, fz);
            f2[3] = pack2(cx, cx); f2[4] = pack2(cy, cy); f2[5] = pack2(cz, cz);
        }

        __syncwarp();
        {
            float* h1row = h1b + (wid * 32 + lane) * 68;
#pragma unroll
            for (int cp = 0; cp < 32; ++cp) {
                const ulonglong4* r4 = (const ulonglong4*)(w1row + cp * 8);
                const ulonglong4 r0 = r4[0];
                const ulonglong4 r1 = r4[1];
                u64 a = mul2(r0.x, f2[0]);
                a = fma2(r0.y, f2[1], a); a = fma2(r0.z, f2[2], a);
                a = fma2(r0.w, f2[3], a); a = fma2(r1.x, f2[4], a);
                a = fma2(r1.y, f2[5], a);
                *(u64*)&h1row[2 * cp] = lrelu2(fma2(a, r1.z, r1.w));
            }
        }
        __syncwarp();

        float d[4][4][4];
#pragma unroll
        for (int m = 0; m < 4; ++m)
#pragma unroll
            for (int n = 0; n < 4; ++n)
#pragma unroll
                for (int i = 0; i < 4; ++i) d[m][n][i] = 0.0f;

#pragma unroll
        for (int k = 0; k < 8; ++k) {
            u32 Bf[4][2];
#pragma unroll
            for (int n = 0; n < 4; ++n)
                LDSM_X2(Bf[n][0], Bf[n][1], b_base + (u32)((n * 8 * 68 + k * 8) * 4));
            u32 Ah[4][4], Al[4][4];
#pragma unroll
            for (int m = 0; m < 4; ++m) {
                const u32 ao = (u32)((m * 16 * 68 + k * 8) * 4);
                LDSM_X4(Ah[m][0], Ah[m][1], Ah[m][2], Ah[m][3], ahi_base + ao);
                LDSM_X4(Al[m][0], Al[m][1], Al[m][2], Al[m][3], alo_base + ao);
            }
#pragma unroll
            for (int m = 0; m < 4; ++m)
#pragma unroll
                for (int n = 0; n < 4; ++n) {
                    MMA_TF32(d[m][n][0], d[m][n][1], d[m][n][2], d[m][n][3],
                             Ah[m][0], Ah[m][1], Ah[m][2], Ah[m][3], Bf[n][0], Bf[n][1]);
                    MMA_TF32(d[m][n][0], d[m][n][1], d[m][n][2], d[m][n][3],
                             Al[m][0], Al[m][1], Al[m][2], Al[m][3], Bf[n][0], Bf[n][1]);
                }
        }

#pragma unroll
        for (int m = 0; m < 4; ++m)
#pragma unroll
            for (int n = 0; n < 4; ++n) {
                d[m][n][0] = lrelu(fmaf(d[m][n][0], s2r[2 * m], b2r[2 * m]));
                d[m][n][1] = lrelu(fmaf(d[m][n][1], s2r[2 * m], b2r[2 * m]));
                d[m][n][2] = lrelu(fmaf(d[m][n][2], s2r[2 * m + 1], b2r[2 * m + 1]));
                d[m][n][3] = lrelu(fmaf(d[m][n][3], s2r[2 * m + 1], b2r[2 * m + 1]));
            }

        float p0f[4], p1f[4];
#pragma unroll
        for (int n = 0; n < 4; ++n) { p0f[n] = 0.0f; p1f[n] = 0.0f; }
#pragma unroll
        for (int m = 0; m < 4; ++m)
#pragma unroll
            for (int n = 0; n < 4; ++n) {
                p0f[n] = fmaf(wa8[2 * m], d[m][n][0], p0f[n]);
                p0f[n] = fmaf(wa8[2 * m + 1], d[m][n][2], p0f[n]);
                p1f[n] = fmaf(wa8[2 * m], d[m][n][1], p1f[n]);
                p1f[n] = fmaf(wa8[2 * m + 1], d[m][n][3], p1f[n]);
            }
#pragma unroll
        for (int n = 0; n < 4; ++n) {
#pragma unroll
            for (int off = 4; off < 32; off <<= 1) {
                p0f[n] += __shfl_xor_sync(FULL, p0f[n], off);
                p1f[n] += __shfl_xor_sync(FULL, p1f[n], off);
            }
        }
        if (lane < 4) {
#pragma unroll
            for (int n = 0; n < 4; ++n) {
                aj_sm[n * 8 + 2 * lane] = p0f[n];
                aj_sm[n * 8 + 2 * lane + 1] = p1f[n];
            }
        }
        __syncwarp();
        float aj = aj_sm[lane];

        aj = lrelu(fmaf(aj + ba0, sa, bza));
        if (lane >= KNBR) aj = -1e30f;
        float mx = aj;
#pragma unroll
        for (int off = 16; off; off >>= 1)
            mx = fmaxf(mx, __shfl_xor_sync(FULL, mx, off));
        const float e = __expf(aj - mx);
        float scn = e;
#pragma unroll
        for (int off = 1; off < 32; off <<= 1) {
            const float v = __shfl_up_sync(FULL, scn, off);
            if (lane >= off) scn += v;
        }
        const float d10 = __shfl_sync(FULL, scn, 9);
        const float d20 = __shfl_sync(FULL, scn, 19);
        const float d30 = __shfl_sync(FULL, scn, 29);
        float ws = 0.0f;
        if (lane < 10) ws += 1.0f / d10;
        if (lane < 20) ws += 1.0f / d20;
        if (lane < 30) ws += 1.0f / d30;
        wrow[lane] = e * ws * (1.0f / 3.0f);
        __syncwarp();

        float w0[4], w1v[4];
#pragma unroll
        for (int n = 0; n < 4; ++n) {
            w0[n] = wrow[n * 8 + 2 * tig];
            w1v[n] = wrow[n * 8 + 2 * tig + 1];
        }
#pragma unroll
        for (int m = 0; m < 4; ++m) {
            float o0 = 0.0f, o1 = 0.0f;
#pragma unroll
            for (int n = 0; n < 4; ++n) {
                o0 = fmaf(d[m][n][0], w0[n], o0);
                o0 = fmaf(d[m][n][1], w1v[n], o0);
                o1 = fmaf(d[m][n][2], w0[n], o1);
                o1 = fmaf(d[m][n][3], w1v[n], o1);
            }
            o0 += __shfl_xor_sync(FULL, o0, 1);
            o0 += __shfl_xor_sync(FULL, o0, 2);
            o1 += __shfl_xor_sync(FULL, o1, 1);
            o1 += __shfl_xor_sync(FULL, o1, 2);
            if (tig == 0) {
                const int row = m * 16 + grp;
                out[(bb * 64 + row) * NPTS + np] = o0;
                out[(bb * 64 + row + 8) * NPTS + np] = o1;
            }
        }
        __syncwarp();
    }
}

extern "C" void kernel_launch(void* const* d_in, const int* in_sizes, int n_in,
                              void* d_out, int out_size) {
    const float* x   = (const float*)d_in[0];
    const float* w1  = (const float*)d_in[1];
    const float* g1  = (const float*)d_in[2];
    const float* b1  = (const float*)d_in[3];
    const float* w2  = (const float*)d_in[4];
    const float* g2  = (const float*)d_in[5];
    const float* b2  = (const float*)d_in[6];
    const float* wa  = (const float*)d_in[7];
    const float* ba  = (const float*)d_in[8];
    const float* ga  = (const float*)d_in[9];
    const float* bga = (const float*)d_in[10];
    float* out = (float*)d_out;

    // one-time host-side resources (no device memory; identical GPU work
    // enqueued every call)
    static cudaStream_t sK = nullptr;
    static cudaEvent_t evFork = nullptr;
    static cudaEvent_t evK[2] = {nullptr, nullptr};
    static bool cfg_done = false;
    if (sK == nullptr) {
        cudaStreamCreateWithFlags(&sK, cudaStreamNonBlocking);
        cudaEventCreateWithFlags(&evFork, cudaEventDisableTiming);
        for (int c = 0; c < 2; ++c)
            cudaEventCreateWithFlags(&evK[c], cudaEventDisableTiming);
    }
    const int knn_smem = NPTS * 16;  // 64KB dynamic
    if (!cfg_done) {
        cudaFuncSetAttribute(knn_kernel, cudaFuncAttributeMaxDynamicSharedMemorySize, knn_smem);
        cudaFuncSetAttribute(mlp_kernel, cudaFuncAttributeMaxDynamicSharedMemorySize, MLP_SMEM);
        cfg_done = true;
    }

    // fork: side stream runs 2 KNN chunks of 4 batches (256 blocks each —
    // full-machine grids); main stream runs MLP chunks gated per-chunk.
    // MLP chunk 0 (~90us) hides under KNN chunk 1 (~125us).
    cudaEventRecord(evFork, 0);
    cudaStreamWaitEvent(sK, evFork, 0);
    for (int c = 0; c < 2; ++c) {
        knn_kernel<<<dim3(NPTS / 64, 4), 512, knn_smem, sK>>>(x, c * 4);
        cudaEventRecord(evK[c], sK);
    }
    for (int c = 0; c < 2; ++c) {
        cudaStreamWaitEvent(0, evK[c], 0);
        mlp_kernel<<<(4 * NPTS) / 32, 128, MLP_SMEM>>>(x, w1, g1, b1, w2, g2, b2,
                                                       wa, ba, ga, bga, out,
                                                       c * 4 * NPTS);
    }
}

// round 15
// speedup vs baseline: 1.2264x; 1.0152x over previous
#include <cuda_runtime.h>
#include <cuda_bf16.h>

#define NPTS 4096
#define BATCH 8
#define KNBR 30
#define NEG_SLOPE 0.2f
#define FULL 0xFFFFFFFFu

typedef unsigned long long u64;
typedef unsigned int u32;

// scratch: neighbor indices [B, N, 30]
__device__ int g_idx[BATCH * NPTS * KNBR];

__device__ __forceinline__ u32 fkey(float f) {
    u32 u = __float_as_uint(f);
    u32 mask = (u32)(((int)u) >> 31) | 0x80000000u;
    return u ^ mask;
}
__device__ __forceinline__ float unfkey(u32 hb) {
    u32 u = (hb & 0x80000000u) ? (hb ^ 0x80000000u) : ~hb;
    return __uint_as_float(u);
}

__device__ __forceinline__ float lrelu(float v) {
    return v > 0.0f ? v : NEG_SLOPE * v;
}

__device__ __forceinline__ u64 pack2(float lo, float hi) {
    u64 r;
    asm("mov.b64 %0, {%1, %2};" : "=l"(r) : "f"(lo), "f"(hi));
    return r;
}
__device__ __forceinline__ void unpack2(u64 v, float& lo, float& hi) {
    asm("mov.b64 {%0, %1}, %2;" : "=f"(lo), "=f"(hi) : "l"(v));
}
__device__ __forceinline__ u64 fma2(u64 a, u64 b, u64 c) {
    u64 d;
    asm("fma.rn.f32x2 %0, %1, %2, %3;" : "=l"(d) : "l"(a), "l"(b), "l"(c));
    return d;
}
__device__ __forceinline__ u64 mul2(u64 a, u64 b) {
    u64 d;
    asm("mul.rn.f32x2 %0, %1, %2;" : "=l"(d) : "l"(a), "l"(b));
    return d;
}
__device__ __forceinline__ u64 add2(u64 a, u64 b) {
    u64 d;
    asm("add.rn.f32x2 %0, %1, %2;" : "=l"(d) : "l"(a), "l"(b));
    return d;
}
__device__ __forceinline__ u64 lrelu2(u64 v) {
    float lo, hi;
    unpack2(v, lo, hi);
    return pack2(lrelu(lo), lrelu(hi));
}
__device__ __forceinline__ u32 f2tf32(float f) {
    u32 r;
    asm("cvt.rna.tf32.f32 %0, %1;" : "=r"(r) : "f"(f));
    return r;
}

#define LDSM_X4(r0, r1, r2, r3, addr)                                        \
    asm volatile("ldmatrix.sync.aligned.m8n8.x4.shared.b16 {%0,%1,%2,%3}, [%4];" \
                 : "=r"(r0), "=r"(r1), "=r"(r2), "=r"(r3) : "r"(addr))
#define LDSM_X2(r0, r1, addr)                                                \
    asm volatile("ldmatrix.sync.aligned.m8n8.x2.shared.b16 {%0,%1}, [%2];"   \
                 : "=r"(r0), "=r"(r1) : "r"(addr))
#define MMA_TF32(d0, d1, d2, d3, a0, a1, a2, a3, b0, b1)                     \
    asm volatile("mma.sync.aligned.m16n8k8.row.col.f32.tf32.tf32.f32 "       \
                 "{%0,%1,%2,%3},{%4,%5,%6,%7},{%8,%9},{%0,%1,%2,%3};"        \
                 : "+f"(d0), "+f"(d1), "+f"(d2), "+f"(d3)                    \
                 : "r"(a0), "r"(a1), "r"(a2), "r"(a3), "r"(b0), "r"(b1))

#define KNN_STEP(M, KEY, L)                                    \
    {                                                          \
        const int src = __ffs(M) - 1;                          \
        M &= M - 1;                                            \
        const u64 k = __shfl_sync(FULL, KEY, src);             \
        u64 prev = __shfl_up_sync(FULL, L, 1);                 \
        if (lane == 0) prev = ~0ull;                           \
        L = (L > k) ? L : ((prev > k) ? k : prev);             \
    }

// ---------------------------------------------------------------------------
// Kernel 1: KNN — warp-per-2-queries; f32x2 dual-candidate scan (lane handles
// candidates c and c+32 per iteration; 64 iterations). Exact u64 rank-insert
// and float-threshold prefilter unchanged (proven).
// smem: XY[2048] ulonglong2 (32KB) + ZW[2048] ulonglong2 (32KB) = 64KB.
//   XY[g*32+l] = { {x_c0,x_c1}, {y_c0,y_c1} },  ZW = { {z_c0,z_c1}, {-w0,-w1} }
//   where c0 = g*64+l, c1 = c0+32.
// ---------------------------------------------------------------------------
__global__ void __launch_bounds__(512) knn_kernel(const float* __restrict__ x) {
    extern __shared__ __align__(16) unsigned char ksm[];
    ulonglong2* XY = (ulonglong2*)ksm;
    ulonglong2* ZW = (ulonglong2*)(ksm + 32768);
    const int b = blockIdx.y;
    const int tid = threadIdx.x;
    const int wid = tid >> 5;
    const int lane = tid & 31;
    const float* xb = x + b * 3 * NPTS;

    for (int i = tid; i < 2048; i += 512) {
        const int g = i >> 5, l = i & 31;
        const int c0 = g * 64 + l, c1 = c0 + 32;
        const float x0 = xb[c0], y0 = xb[NPTS + c0], z0 = xb[2 * NPTS + c0];
        const float x1 = xb[c1], y1 = xb[NPTS + c1], z1 = xb[2 * NPTS + c1];
        const float w0 = x0 * x0 + y0 * y0 + z0 * z0;
        const float w1 = x1 * x1 + y1 * y1 + z1 * z1;
        XY[i] = make_ulonglong2(pack2(x0, x1), pack2(y0, y1));
        ZW[i] = make_ulonglong2(pack2(z0, z1), pack2(-w0, -w1));
    }
    __syncthreads();

    const u64 TWO2 = pack2(2.0f, 2.0f);

    for (int t = 0; t < 2; ++t) {
        const int qA = blockIdx.x * 64 + wid * 4 + t;
        const int qB = qA + 2;
        const float qxA = xb[qA], qyA = xb[NPTS + qA], qzA = xb[2 * NPTS + qA];
        const float qxB = xb[qB], qyB = xb[NPTS + qB], qzB = xb[2 * NPTS + qB];
        const float qqA = qxA * qxA + qyA * qyA + qzA * qzA;
        const float qqB = qxB * qxB + qyB * qyB + qzB * qzB;
        const u64 qxA2 = pack2(qxA, qxA), qyA2 = pack2(qyA, qyA), qzA2 = pack2(qzA, qzA);
        const u64 qxB2 = pack2(qxB, qxB), qyB2 = pack2(qyB, qyB), qzB2 = pack2(qzB, qzB);
        const u64 nqqA2 = pack2(-qqA, -qqA), nqqB2 = pack2(-qqB, -qqB);

        u64 LA = 0ull, LB = 0ull;
        float thrFA = __int_as_float(0xff800000);  // -inf
        float thrFB = __int_as_float(0xff800000);

        for (int g = 0; g < 64; ++g) {
            const ulonglong2 xy = XY[g * 32 + lane];
            const ulonglong2 zw = ZW[g * 32 + lane];
            u64 dA = mul2(qxA2, xy.x);
            dA = fma2(qyA2, xy.y, dA);
            dA = fma2(qzA2, zw.x, dA);
            const u64 pA2 = add2(fma2(TWO2, dA, nqqA2), zw.y);
            u64 dB = mul2(qxB2, xy.x);
            dB = fma2(qyB2, xy.y, dB);
            dB = fma2(qzB2, zw.x, dB);
            const u64 pB2 = add2(fma2(TWO2, dB, nqqB2), zw.y);

            float pdA0, pdA1, pdB0, pdB1;
            unpack2(pA2, pdA0, pdA1);
            unpack2(pB2, pdB0, pdB1);

            unsigned mA0 = __ballot_sync(FULL, pdA0 >= thrFA);
            unsigned mA1 = __ballot_sync(FULL, pdA1 >= thrFA);
            unsigned mB0 = __ballot_sync(FULL, pdB0 >= thrFB);
            unsigned mB1 = __ballot_sync(FULL, pdB1 >= thrFB);
            if (mA0 | mA1 | mB0 | mB1) {
                const bool hA = (mA0 | mA1) != 0u;
                const bool hB = (mB0 | mB1) != 0u;
                const u32 ic0 = (u32)(~(g * 64 + lane));
                const u32 ic1 = (u32)(~(g * 64 + 32 + lane));
                const u64 kA0 = ((u64)fkey(pdA0) << 32) | ic0;
                const u64 kA1 = ((u64)fkey(pdA1) << 32) | ic1;
                const u64 kB0 = ((u64)fkey(pdB0) << 32) | ic0;
                const u64 kB1 = ((u64)fkey(pdB1) << 32) | ic1;
                while (mA0) KNN_STEP(mA0, kA0, LA)
                while (mA1) KNN_STEP(mA1, kA1, LA)
                while (mB0) KNN_STEP(mB0, kB0, LB)
                while (mB1) KNN_STEP(mB1, kB1, LB)
                if (hA) {
                    const u64 thrA = __shfl_sync(FULL, LA, 29);
                    thrFA = unfkey((u32)(thrA >> 32));
                }
                if (hB) {
                    const u64 thrB = __shfl_sync(FULL, LB, 29);
                    thrFB = unfkey((u32)(thrB >> 32));
                }
            }
        }

        if (lane < KNBR) {
            g_idx[(b * NPTS + qA) * KNBR + lane] = (int)(~(u32)LA);
            g_idx[(b * NPTS + qB) * KNBR + lane] = (int)(~(u32)LB);
        }
        __syncwarp();
    }
}

// ---------------------------------------------------------------------------
// Kernel 2: fused edge-MLP; layer-2 on tensor cores (tf32, hi/lo comp).
// Byte-identical to R9/R11 (proven 159us / rel_err 3.58e-4).
// ---------------------------------------------------------------------------
#define SM_WHI 0
#define SM_WLO 17408
#define SM_W1  34816
#define SM_H1  36864
#define SM_AJ  71680
#define MLP_SMEM 72704

__global__ void __launch_bounds__(128, 3) mlp_kernel(
    const float* __restrict__ x,
    const float* __restrict__ w1, const float* __restrict__ g1, const float* __restrict__ b1,
    const float* __restrict__ w2, const float* __restrict__ g2, const float* __restrict__ b2,
    const float* __restrict__ wa, const float* __restrict__ ba,
    const float* __restrict__ ga, const float* __restrict__ bga,
    float* __restrict__ out)
{
    extern __shared__ __align__(16) unsigned char smraw[];
    u32*   whi   = (u32*)(smraw + SM_WHI);
    u32*   wlo   = (u32*)(smraw + SM_WLO);
    u64*   w1row = (u64*)(smraw + SM_W1);
    float* h1b   = (float*)(smraw + SM_H1);
    float* ajwb  = (float*)(smraw + SM_AJ);

    const int tid = threadIdx.x;
    const int wid = tid >> 5;
    const int lane = tid & 31;
    const int grp = lane >> 2;
    const int tig = lane & 3;
    const float rs = rsqrtf(1.0f + 1e-5f);

    for (int idx = tid; idx < 4096; idx += 128) {
        const int c = idx >> 6, k = idx & 63;
        const float w = w2[idx];
        const u32 hb = f2tf32(w);
        const float hf = __uint_as_float(hb);
        whi[c * 68 + k] = hb;
        wlo[c * 68 + k] = f2tf32(w - hf);
    }
    if (tid < 96) {
        const int cp = tid / 3;
        const int i0 = (tid % 3) * 2;
        w1row[cp * 8 + i0] = pack2(w1[(2 * cp) * 6 + i0], w1[(2 * cp + 1) * 6 + i0]);
        w1row[cp * 8 + i0 + 1] = pack2(w1[(2 * cp) * 6 + i0 + 1], w1[(2 * cp + 1) * 6 + i0 + 1]);
    }
    if (tid < 32) {
        w1row[tid * 8 + 6] = pack2(g1[2 * tid] * rs, g1[2 * tid + 1] * rs);
        w1row[tid * 8 + 7] = pack2(b1[2 * tid], b1[2 * tid + 1]);
    }
    __syncthreads();

    float s2r[8], b2r[8], wa8[8];
#pragma unroll
    for (int m = 0; m < 4; ++m) {
        const int r0 = m * 16 + grp, r1 = r0 + 8;
        s2r[2 * m] = g2[r0] * rs;     s2r[2 * m + 1] = g2[r1] * rs;
        b2r[2 * m] = b2[r0];          b2r[2 * m + 1] = b2[r1];
        wa8[2 * m] = wa[r0];          wa8[2 * m + 1] = wa[r1];
    }
    const float ba0 = ba[0];
    const float sa = ga[0] * rs;
    const float bza = bga[0];

    const u32 sb = (u32)__cvta_generic_to_shared(smraw);
    const u32 h1base = sb + SM_H1 + (u32)(wid * 32 * 68 * 4);
    const u32 a_off = (u32)((((lane & 15) * 68) + ((lane >> 4) * 4)) * 4);
    const u32 b_off = (u32)((((lane & 7) * 68) + (((lane >> 3) & 1) * 4)) * 4);
    const u32 ahi_base = sb + SM_WHI + a_off;
    const u32 alo_base = sb + SM_WLO + a_off;
    const u32 b_base = h1base + b_off;

    float* aj_sm = ajwb + wid * 64;
    float* wrow = aj_sm + 32;

    for (int tt = 0; tt < 8; ++tt) {
        const int p = blockIdx.x * 32 + wid * 8 + tt;
        const int bb = p >> 12;
        const int np = p & (NPTS - 1);
        const float* xb = x + bb * 3 * NPTS;
        const float cx = xb[np], cy = xb[NPTS + np], cz = xb[2 * NPTS + np];
        const int nb = (lane < KNBR) ? g_idx[(bb * NPTS + np) * KNBR + lane] : np;

        u64 f2[6];
        {
            const float fx = xb[nb] - cx, fy = xb[NPTS + nb] - cy, fz = xb[2 * NPTS + nb] - cz;
            f2[0] = pack2(fx, fx); f2[1] = pack2(fy, fy); f2[2] = pack2(fz, fz);
            f2[3] = pack2(cx, cx); f2[4] = pack2(cy, cy); f2[5] = pack2(cz, cz);
        }

        __syncwarp();
        {
            float* h1row = h1b + (wid * 32 + lane) * 68;
#pragma unroll
            for (int cp = 0; cp < 32; ++cp) {
                const ulonglong4* r4 = (const ulonglong4*)(w1row + cp * 8);
                const ulonglong4 r0 = r4[0];
                const ulonglong4 r1 = r4[1];
                u64 a = mul2(r0.x, f2[0]);
                a = fma2(r0.y, f2[1], a); a = fma2(r0.z, f2[2], a);
                a = fma2(r0.w, f2[3], a); a = fma2(r1.x, f2[4], a);
                a = fma2(r1.y, f2[5], a);
                *(u64*)&h1row[2 * cp] = lrelu2(fma2(a, r1.z, r1.w));
            }
        }
        __syncwarp();

        float d[4][4][4];
#pragma unroll
        for (int m = 0; m < 4; ++m)
#pragma unroll
            for (int n = 0; n < 4; ++n)
#pragma unroll
                for (int i = 0; i < 4; ++i) d[m][n][i] = 0.0f;

#pragma unroll
        for (int k = 0; k < 8; ++k) {
            u32 Bf[4][2];
#pragma unroll
            for (int n = 0; n < 4; ++n)
                LDSM_X2(Bf[n][0], Bf[n][1], b_base + (u32)((n * 8 * 68 + k * 8) * 4));
            u32 Ah[4][4], Al[4][4];
#pragma unroll
            for (int m = 0; m < 4; ++m) {
                const u32 ao = (u32)((m * 16 * 68 + k * 8) * 4);
                LDSM_X4(Ah[m][0], Ah[m][1], Ah[m][2], Ah[m][3], ahi_base + ao);
                LDSM_X4(Al[m][0], Al[m][1], Al[m][2], Al[m][3], alo_base + ao);
            }
#pragma unroll
            for (int m = 0; m < 4; ++m)
#pragma unroll
                for (int n = 0; n < 4; ++n) {
                    MMA_TF32(d[m][n][0], d[m][n][1], d[m][n][2], d[m][n][3],
                             Ah[m][0], Ah[m][1], Ah[m][2], Ah[m][3], Bf[n][0], Bf[n][1]);
                    MMA_TF32(d[m][n][0], d[m][n][1], d[m][n][2], d[m][n][3],
                             Al[m][0], Al[m][1], Al[m][2], Al[m][3], Bf[n][0], Bf[n][1]);
                }
        }

#pragma unroll
        for (int m = 0; m < 4; ++m)
#pragma unroll
            for (int n = 0; n < 4; ++n) {
                d[m][n][0] = lrelu(fmaf(d[m][n][0], s2r[2 * m], b2r[2 * m]));
                d[m][n][1] = lrelu(fmaf(d[m][n][1], s2r[2 * m], b2r[2 * m]));
                d[m][n][2] = lrelu(fmaf(d[m][n][2], s2r[2 * m + 1], b2r[2 * m + 1]));
                d[m][n][3] = lrelu(fmaf(d[m][n][3], s2r[2 * m + 1], b2r[2 * m + 1]));
            }

        float p0f[4], p1f[4];
#pragma unroll
        for (int n = 0; n < 4; ++n) { p0f[n] = 0.0f; p1f[n] = 0.0f; }
#pragma unroll
        for (int m = 0; m < 4; ++m)
#pragma unroll
            for (int n = 0; n < 4; ++n) {
                p0f[n] = fmaf(wa8[2 * m], d[m][n][0], p0f[n]);
                p0f[n] = fmaf(wa8[2 * m + 1], d[m][n][2], p0f[n]);
                p1f[n] = fmaf(wa8[2 * m], d[m][n][1], p1f[n]);
                p1f[n] = fmaf(wa8[2 * m + 1], d[m][n][3], p1f[n]);
            }
#pragma unroll
        for (int n = 0; n < 4; ++n) {
#pragma unroll
            for (int off = 4; off < 32; off <<= 1) {
                p0f[n] += __shfl_xor_sync(FULL, p0f[n], off);
                p1f[n] += __shfl_xor_sync(FULL, p1f[n], off);
            }
        }
        if (lane < 4) {
#pragma unroll
            for (int n = 0; n < 4; ++n) {
                aj_sm[n * 8 + 2 * lane] = p0f[n];
                aj_sm[n * 8 + 2 * lane + 1] = p1f[n];
            }
        }
        __syncwarp();
        float aj = aj_sm[lane];

        aj = lrelu(fmaf(aj + ba0, sa, bza));
        if (lane >= KNBR) aj = -1e30f;
        float mx = aj;
#pragma unroll
        for (int off = 16; off; off >>= 1)
            mx = fmaxf(mx, __shfl_xor_sync(FULL, mx, off));
        const float e = __expf(aj - mx);
        float scn = e;
#pragma unroll
        for (int off = 1; off < 32; off <<= 1) {
            const float v = __shfl_up_sync(FULL, scn, off);
            if (lane >= off) scn += v;
        }
        const float d10 = __shfl_sync(FULL, scn, 9);
        const float d20 = __shfl_sync(FULL, scn, 19);
        const float d30 = __shfl_sync(FULL, scn, 29);
        float ws = 0.0f;
        if (lane < 10) ws += 1.0f / d10;
        if (lane < 20) ws += 1.0f / d20;
        if (lane < 30) ws += 1.0f / d30;
        wrow[lane] = e * ws * (1.0f / 3.0f);
        __syncwarp();

        float w0[4], w1v[4];
#pragma unroll
        for (int n = 0; n < 4; ++n) {
            w0[n] = wrow[n * 8 + 2 * tig];
            w1v[n] = wrow[n * 8 + 2 * tig + 1];
        }
#pragma unroll
        for (int m = 0; m < 4; ++m) {
            float o0 = 0.0f, o1 = 0.0f;
#pragma unroll
            for (int n = 0; n < 4; ++n) {
                o0 = fmaf(d[m][n][0], w0[n], o0);
                o0 = fmaf(d[m][n][1], w1v[n], o0);
                o1 = fmaf(d[m][n][2], w0[n], o1);
                o1 = fmaf(d[m][n][3], w1v[n], o1);
            }
            o0 += __shfl_xor_sync(FULL, o0, 1);
            o0 += __shfl_xor_sync(FULL, o0, 2);
            o1 += __shfl_xor_sync(FULL, o1, 1);
            o1 += __shfl_xor_sync(FULL, o1, 2);
            if (tig == 0) {
                const int row = m * 16 + grp;
                out[(bb * 64 + row) * NPTS + np] = o0;
                out[(bb * 64 + row + 8) * NPTS + np] = o1;
            }
        }
        __syncwarp();
    }
}

extern "C" void kernel_launch(void* const* d_in, const int* in_sizes, int n_in,
                              void* d_out, int out_size) {
    const float* x   = (const float*)d_in[0];
    const float* w1  = (const float*)d_in[1];
    const float* g1  = (const float*)d_in[2];
    const float* b1  = (const float*)d_in[3];
    const float* w2  = (const float*)d_in[4];
    const float* g2  = (const float*)d_in[5];
    const float* b2  = (const float*)d_in[6];
    const float* wa  = (const float*)d_in[7];
    const float* ba  = (const float*)d_in[8];
    const float* ga  = (const float*)d_in[9];
    const float* bga = (const float*)d_in[10];
    float* out = (float*)d_out;

    const int knn_smem = 65536;  // XY + ZW, 64KB dynamic
    cudaFuncSetAttribute(knn_kernel, cudaFuncAttributeMaxDynamicSharedMemorySize, knn_smem);
    cudaFuncSetAttribute(mlp_kernel, cudaFuncAttributeMaxDynamicSharedMemorySize, MLP_SMEM);

    knn_kernel<<<dim3(NPTS / 64, BATCH), 512, knn_smem>>>(x);
    mlp_kernel<<<(BATCH * NPTS) / 32, 128, MLP_SMEM>>>(x, w1, g1, b1, w2, g2, b2,
                                                       wa, ba, ga, bga, out);
}

// round 16
// speedup vs baseline: 1.3405x; 1.0930x over previous
#include <cuda_runtime.h>
#include <cuda_bf16.h>

#define NPTS 4096
#define BATCH 8
#define KNBR 30
#define NEG_SLOPE 0.2f
#define FULL 0xFFFFFFFFu

typedef unsigned long long u64;
typedef unsigned int u32;

// scratch: neighbor indices [B, N, 30]
__device__ int g_idx[BATCH * NPTS * KNBR];

__device__ __forceinline__ u32 fkey(float f) {
    u32 u = __float_as_uint(f);
    u32 mask = (u32)(((int)u) >> 31) | 0x80000000u;
    return u ^ mask;
}
__device__ __forceinline__ float unfkey(u32 hb) {
    u32 u = (hb & 0x80000000u) ? (hb ^ 0x80000000u) : ~hb;
    return __uint_as_float(u);
}

__device__ __forceinline__ float lrelu(float v) {
    return v > 0.0f ? v : NEG_SLOPE * v;
}

__device__ __forceinline__ u64 pack2(float lo, float hi) {
    u64 r;
    asm("mov.b64 %0, {%1, %2};" : "=l"(r) : "f"(lo), "f"(hi));
    return r;
}
__device__ __forceinline__ void unpack2(u64 v, float& lo, float& hi) {
    asm("mov.b64 {%0, %1}, %2;" : "=f"(lo), "=f"(hi) : "l"(v));
}
__device__ __forceinline__ u64 fma2(u64 a, u64 b, u64 c) {
    u64 d;
    asm("fma.rn.f32x2 %0, %1, %2, %3;" : "=l"(d) : "l"(a), "l"(b), "l"(c));
    return d;
}
__device__ __forceinline__ u64 mul2(u64 a, u64 b) {
    u64 d;
    asm("mul.rn.f32x2 %0, %1, %2;" : "=l"(d) : "l"(a), "l"(b));
    return d;
}
__device__ __forceinline__ u64 lrelu2(u64 v) {
    float lo, hi;
    unpack2(v, lo, hi);
    return pack2(lrelu(lo), lrelu(hi));
}
__device__ __forceinline__ u32 f2tf32(float f) {
    u32 r;
    asm("cvt.rna.tf32.f32 %0, %1;" : "=r"(r) : "f"(f));
    return r;
}

#define LDSM_X4(r0, r1, r2, r3, addr)                                        \
    asm volatile("ldmatrix.sync.aligned.m8n8.x4.shared.b16 {%0,%1,%2,%3}, [%4];" \
                 : "=r"(r0), "=r"(r1), "=r"(r2), "=r"(r3) : "r"(addr))
#define LDSM_X2(r0, r1, addr)                                                \
    asm volatile("ldmatrix.sync.aligned.m8n8.x2.shared.b16 {%0,%1}, [%2];"   \
                 : "=r"(r0), "=r"(r1) : "r"(addr))
#define MMA_TF32(d0, d1, d2, d3, a0, a1, a2, a3, b0, b1)                     \
    asm volatile("mma.sync.aligned.m16n8k8.row.col.f32.tf32.tf32.f32 "       \
                 "{%0,%1,%2,%3},{%4,%5,%6,%7},{%8,%9},{%0,%1,%2,%3};"        \
                 : "+f"(d0), "+f"(d1), "+f"(d2), "+f"(d3)                    \
                 : "r"(a0), "r"(a1), "r"(a2), "r"(a3), "r"(b0), "r"(b1))

// ---------------------------------------------------------------------------
// Kernel 1: KNN — warp-per-2-queries, float prefilter (R11, proven best).
// ---------------------------------------------------------------------------
__global__ void __launch_bounds__(512) knn_kernel(const float* __restrict__ x) {
    extern __shared__ float4 p4[];
    const int b = blockIdx.y;
    const int tid = threadIdx.x;
    const int wid = tid >> 5;
    const int lane = tid & 31;
    const float* xb = x + b * 3 * NPTS;

    for (int i = tid; i < NPTS; i += 512) {
        float cx = xb[i], cy = xb[NPTS + i], cz = xb[2 * NPTS + i];
        p4[i] = make_float4(cx, cy, cz, cx * cx + cy * cy + cz * cz);
    }
    __syncthreads();

    for (int t = 0; t < 2; ++t) {
        const int qA = blockIdx.x * 64 + wid * 4 + t;
        const int qB = qA + 2;
        const float4 qvA = p4[qA];
        const float4 qvB = p4[qB];
        const float qqA = qvA.w, qqB = qvB.w;

        u64 LA = 0ull, LB = 0ull;
        float thrFA = __int_as_float(0xff800000);
        float thrFB = __int_as_float(0xff800000);

#pragma unroll 2
        for (int base = 0; base < NPTS; base += 32) {
            const int c = base + lane;
            const float4 cv = p4[c];
            float dA = qvA.x * cv.x;
            dA = fmaf(qvA.y, cv.y, dA);
            dA = fmaf(qvA.z, cv.z, dA);
            float dB = qvB.x * cv.x;
            dB = fmaf(qvB.y, cv.y, dB);
            dB = fmaf(qvB.z, cv.z, dB);
            const float pdA = fmaf(2.0f, dA, -qqA) - cv.w;
            const float pdB = fmaf(2.0f, dB, -qqB) - cv.w;

            unsigned mA = __ballot_sync(FULL, pdA >= thrFA);
            unsigned mB = __ballot_sync(FULL, pdB >= thrFB);
            if (mA | mB) {
                const u32 ic = (u32)(~c);
                const u64 keyA = ((u64)fkey(pdA) << 32) | ic;
                const u64 keyB = ((u64)fkey(pdB) << 32) | ic;
                while (mA) {
                    const int src = __ffs(mA) - 1;
                    mA &= mA - 1;
                    const u64 k = __shfl_sync(FULL, keyA, src);
                    u64 prev = __shfl_up_sync(FULL, LA, 1);
                    if (lane == 0) prev = ~0ull;
                    LA = (LA > k) ? LA : ((prev > k) ? k : prev);
                }
                while (mB) {
                    const int src = __ffs(mB) - 1;
                    mB &= mB - 1;
                    const u64 k = __shfl_sync(FULL, keyB, src);
                    u64 prev = __shfl_up_sync(FULL, LB, 1);
                    if (lane == 0) prev = ~0ull;
                    LB = (LB > k) ? LB : ((prev > k) ? k : prev);
                }
                const u64 thrA = __shfl_sync(FULL, LA, 29);
                const u64 thrB = __shfl_sync(FULL, LB, 29);
                thrFA = unfkey((u32)(thrA >> 32));
                thrFB = unfkey((u32)(thrB >> 32));
            }
        }

        if (lane < KNBR) {
            g_idx[(b * NPTS + qA) * KNBR + lane] = (int)(~(u32)LA);
            g_idx[(b * NPTS + qB) * KNBR + lane] = (int)(~(u32)LB);
        }
        __syncwarp();
    }
}

// ---------------------------------------------------------------------------
// Kernel 2: fused edge-MLP; layer-2 on tensor cores — SINGLE-PASS tf32
// (w2 hi only; lo-compensation dropped). Halves MMA and A-fragment loads.
// ---------------------------------------------------------------------------
#define SM_WHI 0
#define SM_W1  17408
#define SM_H1  19456
#define SM_AJ  54272
#define MLP_SMEM 55296

__global__ void __launch_bounds__(128, 3) mlp_kernel(
    const float* __restrict__ x,
    const float* __restrict__ w1, const float* __restrict__ g1, const float* __restrict__ b1,
    const float* __restrict__ w2, const float* __restrict__ g2, const float* __restrict__ b2,
    const float* __restrict__ wa, const float* __restrict__ ba,
    const float* __restrict__ ga, const float* __restrict__ bga,
    float* __restrict__ out)
{
    extern __shared__ __align__(16) unsigned char smraw[];
    u32*   whi   = (u32*)(smraw + SM_WHI);
    u64*   w1row = (u64*)(smraw + SM_W1);
    float* h1b   = (float*)(smraw + SM_H1);
    float* ajwb  = (float*)(smraw + SM_AJ);

    const int tid = threadIdx.x;
    const int wid = tid >> 5;
    const int lane = tid & 31;
    const int grp = lane >> 2;
    const int tig = lane & 3;
    const float rs = rsqrtf(1.0f + 1e-5f);

    for (int idx = tid; idx < 4096; idx += 128) {
        const int c = idx >> 6, k = idx & 63;
        whi[c * 68 + k] = f2tf32(w2[idx]);
    }
    if (tid < 96) {
        const int cp = tid / 3;
        const int i0 = (tid % 3) * 2;
        w1row[cp * 8 + i0] = pack2(w1[(2 * cp) * 6 + i0], w1[(2 * cp + 1) * 6 + i0]);
        w1row[cp * 8 + i0 + 1] = pack2(w1[(2 * cp) * 6 + i0 + 1], w1[(2 * cp + 1) * 6 + i0 + 1]);
    }
    if (tid < 32) {
        w1row[tid * 8 + 6] = pack2(g1[2 * tid] * rs, g1[2 * tid + 1] * rs);
        w1row[tid * 8 + 7] = pack2(b1[2 * tid], b1[2 * tid + 1]);
    }
    __syncthreads();

    float s2r[8], b2r[8], wa8[8];
#pragma unroll
    for (int m = 0; m < 4; ++m) {
        const int r0 = m * 16 + grp, r1 = r0 + 8;
        s2r[2 * m] = g2[r0] * rs;     s2r[2 * m + 1] = g2[r1] * rs;
        b2r[2 * m] = b2[r0];          b2r[2 * m + 1] = b2[r1];
        wa8[2 * m] = wa[r0];          wa8[2 * m + 1] = wa[r1];
    }
    const float ba0 = ba[0];
    const float sa = ga[0] * rs;
    const float bza = bga[0];

    const u32 sb = (u32)__cvta_generic_to_shared(smraw);
    const u32 h1base = sb + SM_H1 + (u32)(wid * 32 * 68 * 4);
    const u32 a_off = (u32)((((lane & 15) * 68) + ((lane >> 4) * 4)) * 4);
    const u32 b_off = (u32)((((lane & 7) * 68) + (((lane >> 3) & 1) * 4)) * 4);
    const u32 ahi_base = sb + SM_WHI + a_off;
    const u32 b_base = h1base + b_off;

    float* aj_sm = ajwb + wid * 64;
    float* wrow = aj_sm + 32;

    for (int tt = 0; tt < 8; ++tt) {
        const int p = blockIdx.x * 32 + wid * 8 + tt;
        const int bb = p >> 12;
        const int np = p & (NPTS - 1);
        const float* xb = x + bb * 3 * NPTS;
        const float cx = xb[np], cy = xb[NPTS + np], cz = xb[2 * NPTS + np];
        const int nb = (lane < KNBR) ? g_idx[(bb * NPTS + np) * KNBR + lane] : np;

        u64 f2[6];
        {
            const float fx = xb[nb] - cx, fy = xb[NPTS + nb] - cy, fz = xb[2 * NPTS + nb] - cz;
            f2[0] = pack2(fx, fx); f2[1] = pack2(fy, fy); f2[2] = pack2(fz, fz);
            f2[3] = pack2(cx, cx); f2[4] = pack2(cy, cy); f2[5] = pack2(cz, cz);
        }

        __syncwarp();
        {
            float* h1row = h1b + (wid * 32 + lane) * 68;
#pragma unroll
            for (int cp = 0; cp < 32; ++cp) {
                const ulonglong4* r4 = (const ulonglong4*)(w1row + cp * 8);
                const ulonglong4 r0 = r4[0];
                const ulonglong4 r1 = r4[1];
                u64 a = mul2(r0.x, f2[0]);
                a = fma2(r0.y, f2[1], a); a = fma2(r0.z, f2[2], a);
                a = fma2(r0.w, f2[3], a); a = fma2(r1.x, f2[4], a);
                a = fma2(r1.y, f2[5], a);
                *(u64*)&h1row[2 * cp] = lrelu2(fma2(a, r1.z, r1.w));
            }
        }
        __syncwarp();

        float d[4][4][4];
#pragma unroll
        for (int m = 0; m < 4; ++m)
#pragma unroll
            for (int n = 0; n < 4; ++n)
#pragma unroll
                for (int i = 0; i < 4; ++i) d[m][n][i] = 0.0f;

#pragma unroll
        for (int k = 0; k < 8; ++k) {
            u32 Bf[4][2];
#pragma unroll
            for (int n = 0; n < 4; ++n)
                LDSM_X2(Bf[n][0], Bf[n][1], b_base + (u32)((n * 8 * 68 + k * 8) * 4));
            u32 Ah[4][4];
#pragma unroll
            for (int m = 0; m < 4; ++m) {
                const u32 ao = (u32)((m * 16 * 68 + k * 8) * 4);
                LDSM_X4(Ah[m][0], Ah[m][1], Ah[m][2], Ah[m][3], ahi_base + ao);
            }
#pragma unroll
            for (int m = 0; m < 4; ++m)
#pragma unroll
                for (int n = 0; n < 4; ++n) {
                    MMA_TF32(d[m][n][0], d[m][n][1], d[m][n][2], d[m][n][3],
                             Ah[m][0], Ah[m][1], Ah[m][2], Ah[m][3], Bf[n][0], Bf[n][1]);
                }
        }

#pragma unroll
        for (int m = 0; m < 4; ++m)
#pragma unroll
            for (int n = 0; n < 4; ++n) {
                d[m][n][0] = lrelu(fmaf(d[m][n][0], s2r[2 * m], b2r[2 * m]));
                d[m][n][1] = lrelu(fmaf(d[m][n][1], s2r[2 * m], b2r[2 * m]));
                d[m][n][2] = lrelu(fmaf(d[m][n][2], s2r[2 * m + 1], b2r[2 * m + 1]));
                d[m][n][3] = lrelu(fmaf(d[m][n][3], s2r[2 * m + 1], b2r[2 * m + 1]));
            }

        float p0f[4], p1f[4];
#pragma unroll
        for (int n = 0; n < 4; ++n) { p0f[n] = 0.0f; p1f[n] = 0.0f; }
#pragma unroll
        for (int m = 0; m < 4; ++m)
#pragma unroll
            for (int n = 0; n < 4; ++n) {
                p0f[n] = fmaf(wa8[2 * m], d[m][n][0], p0f[n]);
                p0f[n] = fmaf(wa8[2 * m + 1], d[m][n][2], p0f[n]);
                p1f[n] = fmaf(wa8[2 * m], d[m][n][1], p1f[n]);
                p1f[n] = fmaf(wa8[2 * m + 1], d[m][n][3], p1f[n]);
            }
#pragma unroll
        for (int n = 0; n < 4; ++n) {
#pragma unroll
            for (int off = 4; off < 32; off <<= 1) {
                p0f[n] += __shfl_xor_sync(FULL, p0f[n], off);
                p1f[n] += __shfl_xor_sync(FULL, p1f[n], off);
            }
        }
        if (lane < 4) {
#pragma unroll
            for (int n = 0; n < 4; ++n) {
                aj_sm[n * 8 + 2 * lane] = p0f[n];
                aj_sm[n * 8 + 2 * lane + 1] = p1f[n];
            }
        }
        __syncwarp();
        float aj = aj_sm[lane];

        aj = lrelu(fmaf(aj + ba0, sa, bza));
        if (lane >= KNBR) aj = -1e30f;
        float mx = aj;
#pragma unroll
        for (int off = 16; off; off >>= 1)
            mx = fmaxf(mx, __shfl_xor_sync(FULL, mx, off));
        const float e = __expf(aj - mx);
        float scn = e;
#pragma unroll
        for (int off = 1; off < 32; off <<= 1) {
            const float v = __shfl_up_sync(FULL, scn, off);
            if (lane >= off) scn += v;
        }
        const float d10 = __shfl_sync(FULL, scn, 9);
        const float d20 = __shfl_sync(FULL, scn, 19);
        const float d30 = __shfl_sync(FULL, scn, 29);
        float ws = 0.0f;
        if (lane < 10) ws += 1.0f / d10;
        if (lane < 20) ws += 1.0f / d20;
        if (lane < 30) ws += 1.0f / d30;
        wrow[lane] = e * ws * (1.0f / 3.0f);
        __syncwarp();

        float w0[4], w1v[4];
#pragma unroll
        for (int n = 0; n < 4; ++n) {
            w0[n] = wrow[n * 8 + 2 * tig];
            w1v[n] = wrow[n * 8 + 2 * tig + 1];
        }
#pragma unroll
        for (int m = 0; m < 4; ++m) {
            float o0 = 0.0f, o1 = 0.0f;
#pragma unroll
            for (int n = 0; n < 4; ++n) {
                o0 = fmaf(d[m][n][0], w0[n], o0);
                o0 = fmaf(d[m][n][1], w1v[n], o0);
                o1 = fmaf(d[m][n][2], w0[n], o1);
                o1 = fmaf(d[m][n][3], w1v[n], o1);
            }
            o0 += __shfl_xor_sync(FULL, o0, 1);
            o0 += __shfl_xor_sync(FULL, o0, 2);
            o1 += __shfl_xor_sync(FULL, o1, 1);
            o1 += __shfl_xor_sync(FULL, o1, 2);
            if (tig == 0) {
                const int row = m * 16 + grp;
                out[(bb * 64 + row) * NPTS + np] = o0;
                out[(bb * 64 + row + 8) * NPTS + np] = o1;
            }
        }
        __syncwarp();
    }
}

extern "C" void kernel_launch(void* const* d_in, const int* in_sizes, int n_in,
                              void* d_out, int out_size) {
    const float* x   = (const float*)d_in[0];
    const float* w1  = (const float*)d_in[1];
    const float* g1  = (const float*)d_in[2];
    const float* b1  = (const float*)d_in[3];
    const float* w2  = (const float*)d_in[4];
    const float* g2  = (const float*)d_in[5];
    const float* b2  = (const float*)d_in[6];
    const float* wa  = (const float*)d_in[7];
    const float* ba  = (const float*)d_in[8];
    const float* ga  = (const float*)d_in[9];
    const float* bga = (const float*)d_in[10];
    float* out = (float*)d_out;

    const int knn_smem = NPTS * 16;  // 64KB dynamic
    cudaFuncSetAttribute(knn_kernel, cudaFuncAttributeMaxDynamicSharedMemorySize, knn_smem);
    cudaFuncSetAttribute(mlp_kernel, cudaFuncAttributeMaxDynamicSharedMemorySize, MLP_SMEM);

    knn_kernel<<<dim3(NPTS / 64, BATCH), 512, knn_smem>>>(x);
    mlp_kernel<<<(BATCH * NPTS) / 32, 128, MLP_SMEM>>>(x, w1, g1, b1, w2, g2, b2,
                                                       wa, ba, ga, bga, out);
}